// round 1
// baseline (speedup 1.0000x reference)
#include <cuda_runtime.h>
#include <cuda_bf16.h>
#include <math.h>

// ---------------------------------------------------------------------------
// Problem constants
// ---------------------------------------------------------------------------
#define VEG 4
#define WEA 8
#define HID 512
#define NB  256
#define T_HIST 150
#define T_FUT  50
#define XK_SMALL (VEG + WEA)   // 12
#define HB (NB * HID)          // 131072 floats per (h,c) state

// ---------------------------------------------------------------------------
// Device scratch (static allocation only — no cudaMalloc allowed)
// ---------------------------------------------------------------------------
__device__ float g_xhist[T_HIST * NB * XK_SMALL];  // [t][b][12]
__device__ float g_y0[T_HIST * NB * HID];          // layer0 outputs, [t][b][u]  (78.6 MB)
__device__ float g_zero[HB];
__device__ float g_c0[HB];
__device__ float g_c1[HB];
__device__ float g_h1a[HB];
__device__ float g_h1b[HB];
__device__ float g_h0a[HB];
__device__ float g_h0b[HB];
__device__ float g_pred[NB * VEG];
__device__ float g_xdec[NB * XK_SMALL];

// ---------------------------------------------------------------------------
// Activation helpers (fast, ~1e-7 rel err)
// ---------------------------------------------------------------------------
__device__ __forceinline__ float sigmoidf_(float x) {
    return 1.0f / (1.0f + __expf(-x));
}
__device__ __forceinline__ float tanhf_(float x) {
    // 2*sigmoid(2x)-1 ; handles +/-inf correctly
    return 2.0f / (1.0f + __expf(-2.0f * x)) - 1.0f;
}

// ---------------------------------------------------------------------------
// prep: smoothing + concat -> g_xhist ; also init pred / first decoder x
// ---------------------------------------------------------------------------
__global__ void prep_kernel(const float* __restrict__ veg,
                            const float* __restrict__ wh,
                            const float* __restrict__ wf,
                            float* __restrict__ xhist,
                            float* __restrict__ pred,
                            float* __restrict__ xdec) {
    int b = threadIdx.x;   // 256
    int t = blockIdx.x;    // 150
    float vs[VEG];
#pragma unroll
    for (int v = 0; v < VEG; v++) {
        float val = veg[b * (T_HIST * VEG) + t * VEG + v];
        float s = 0.f;
#pragma unroll
        for (int dt = -2; dt <= 2; dt++) {
            int tt = t + dt;
            if (tt >= 0 && tt < T_HIST) {
                float u = veg[b * (T_HIST * VEG) + tt * VEG + v];
                if (!isnan(u)) s += u;
            }
        }
        float sm = s * 0.2f;
        float outv = isnan(val) ? sm : val;
        if (isnan(outv)) outv = 0.f;
        vs[v] = outv;
        xhist[(t * NB + b) * XK_SMALL + v] = outv;
    }
#pragma unroll
    for (int k = 0; k < WEA; k++)
        xhist[(t * NB + b) * XK_SMALL + VEG + k] = wh[b * (T_HIST * WEA) + t * WEA + k];

    if (t == T_HIST - 1) {
#pragma unroll
        for (int v = 0; v < VEG; v++) {
            pred[b * VEG + v] = vs[v];
            xdec[b * XK_SMALL + v] = vs[v];
        }
#pragma unroll
        for (int k = 0; k < WEA; k++)
            xdec[b * XK_SMALL + VEG + k] = wf[b * (T_FUT * WEA) + k];  // forecast t=0
    }
}

__global__ void zero_kernel(float* __restrict__ z, float* __restrict__ c0,
                            float* __restrict__ c1) {
    int i = blockIdx.x * blockDim.x + threadIdx.x;
    if (i < HB) { z[i] = 0.f; c0[i] = 0.f; c1[i] = 0.f; }
}

// ---------------------------------------------------------------------------
// Fused LSTM cell step
//   gates[b][g*512+u] = h_prev[b]·Whh[g*512+u] + x[b]·Wih[g*512+u] + bias
//   then elementwise -> c (inplace), h_out
// Block tile: 64 batches x 16 units (= 64 gate columns). 256 threads.
// Thread (ul = tid&15, mg = tid>>4): batches mg*4..+3, unit ul, 4 gates.
// ---------------------------------------------------------------------------
#define KC 32
#define SMS 68   // padded smem row stride (floats)

__device__ __forceinline__ void gemm_phase(
    const float* __restrict__ W,    // [2048][512]
    const float* __restrict__ X,    // [256][512] operand (h or wide x)
    int bbase, int ubase, int tid,
    float acc[4][4],
    float Hs[KC][SMS], float Ws[KC][SMS]) {

    const int kq = tid & 7;
    const int jb = tid >> 3;   // 0..31
    const int mg = tid >> 4;   // 0..15
    const int ul = tid & 15;   // 0..15

    for (int k0 = 0; k0 < HID; k0 += KC) {
#pragma unroll
        for (int r = 0; r < 2; r++) {
            int b = jb + r * 32;
            float4 hv = *reinterpret_cast<const float4*>(
                &X[(bbase + b) * HID + k0 + kq * 4]);
            Hs[kq * 4 + 0][b] = hv.x; Hs[kq * 4 + 1][b] = hv.y;
            Hs[kq * 4 + 2][b] = hv.z; Hs[kq * 4 + 3][b] = hv.w;

            int j = jb + r * 32;            // j = u*4 + g
            int g = j & 3, u = j >> 2;
            float4 wv = *reinterpret_cast<const float4*>(
                &W[(g * HID + ubase + u) * HID + k0 + kq * 4]);
            Ws[kq * 4 + 0][j] = wv.x; Ws[kq * 4 + 1][j] = wv.y;
            Ws[kq * 4 + 2][j] = wv.z; Ws[kq * 4 + 3][j] = wv.w;
        }
        __syncthreads();
#pragma unroll
        for (int k = 0; k < KC; k++) {
            float4 h4 = *reinterpret_cast<const float4*>(&Hs[k][mg * 4]);
            float4 w4 = *reinterpret_cast<const float4*>(&Ws[k][ul * 4]);
            acc[0][0] += h4.x * w4.x; acc[0][1] += h4.x * w4.y;
            acc[0][2] += h4.x * w4.z; acc[0][3] += h4.x * w4.w;
            acc[1][0] += h4.y * w4.x; acc[1][1] += h4.y * w4.y;
            acc[1][2] += h4.y * w4.z; acc[1][3] += h4.y * w4.w;
            acc[2][0] += h4.z * w4.x; acc[2][1] += h4.z * w4.y;
            acc[2][2] += h4.z * w4.z; acc[2][3] += h4.z * w4.w;
            acc[3][0] += h4.w * w4.x; acc[3][1] += h4.w * w4.y;
            acc[3][2] += h4.w * w4.z; acc[3][3] += h4.w * w4.w;
        }
        __syncthreads();
    }
}

template <bool BIG_X>
__global__ void __launch_bounds__(256)
cell_kernel(const float* __restrict__ xin,     // [256][12] or [256][512]
            const float* __restrict__ hprev,   // [256][512]
            float* __restrict__ c,             // [256][512] (inplace)
            float* __restrict__ hout,          // [256][512]
            const float* __restrict__ Wih,     // [2048][12] or [2048][512]
            const float* __restrict__ Whh,     // [2048][512]
            const float* __restrict__ bias) {  // [2048]
    __shared__ __align__(16) float Hs[KC][SMS];
    __shared__ __align__(16) float Ws[KC][SMS];

    const int tid = threadIdx.x;
    const int bbase = blockIdx.x * 64;
    const int ubase = blockIdx.y * 16;
    const int mg = tid >> 4;
    const int ul = tid & 15;

    float acc[4][4];
#pragma unroll
    for (int i = 0; i < 4; i++)
#pragma unroll
        for (int g = 0; g < 4; g++) acc[i][g] = 0.f;

    gemm_phase(Whh, hprev, bbase, ubase, tid, acc, Hs, Ws);

    if (BIG_X) {
        gemm_phase(Wih, xin, bbase, ubase, tid, acc, Hs, Ws);
    } else {
        // small input contribution (K = 12), staged in smem
        float* Xs = &Hs[0][0];   // [64][12]
        float* WX = &Ws[0][0];   // [64][12], row j = u*4+g
        for (int idx = tid; idx < 64 * XK_SMALL; idx += 256) {
            int b = idx / XK_SMALL, k = idx - b * XK_SMALL;
            Xs[idx] = xin[(bbase + b) * XK_SMALL + k];
            int j = b;  // reuse decomposition for weights
            int g = j & 3, u = j >> 2;
            WX[idx] = Wih[(g * HID + ubase + u) * XK_SMALL + k];
        }
        __syncthreads();
#pragma unroll
        for (int k = 0; k < XK_SMALL; k++) {
            float xv[4], wv[4];
#pragma unroll
            for (int i = 0; i < 4; i++) xv[i] = Xs[(mg * 4 + i) * XK_SMALL + k];
#pragma unroll
            for (int g = 0; g < 4; g++) wv[g] = WX[(ul * 4 + g) * XK_SMALL + k];
#pragma unroll
            for (int i = 0; i < 4; i++)
#pragma unroll
                for (int g = 0; g < 4; g++) acc[i][g] += xv[i] * wv[g];
        }
    }

    // epilogue: bias + gates + state update
    const int unit = ubase + ul;
    const float bv0 = bias[0 * HID + unit];
    const float bv1 = bias[1 * HID + unit];
    const float bv2 = bias[2 * HID + unit];
    const float bv3 = bias[3 * HID + unit];
#pragma unroll
    for (int i = 0; i < 4; i++) {
        int b = bbase + mg * 4 + i;
        int idx = b * HID + unit;
        float gi = sigmoidf_(acc[i][0] + bv0);
        float gf = sigmoidf_(acc[i][1] + bv1);
        float gg = tanhf_(acc[i][2] + bv2);
        float go = sigmoidf_(acc[i][3] + bv3);
        float cn = gf * c[idx] + gi * gg;
        c[idx] = cn;
        hout[idx] = go * tanhf_(cn);
    }
}

// ---------------------------------------------------------------------------
// head: pred += h1 @ headW^T + headb ; write output[t]; build next decoder x
// ---------------------------------------------------------------------------
__global__ void head_kernel(const float* __restrict__ h1,
                            const float* __restrict__ headW,
                            const float* __restrict__ headb,
                            float* __restrict__ pred,
                            float* __restrict__ out_t,     // d_out + t*4
                            const float* __restrict__ wf_next,  // wf + (t+1)*8 or null
                            float* __restrict__ xdec) {
    int b = blockIdx.x;
    int w = threadIdx.x >> 5;     // v index 0..3
    int lane = threadIdx.x & 31;
    const float* hr = &h1[b * HID];
    const float* wr = &headW[w * HID];
    float s = 0.f;
    for (int k = lane; k < HID; k += 32) s += hr[k] * wr[k];
#pragma unroll
    for (int o = 16; o; o >>= 1) s += __shfl_down_sync(0xffffffffu, s, o);
    if (lane == 0) {
        float p = pred[b * VEG + w] + s + headb[w];
        pred[b * VEG + w] = p;
        out_t[b * (T_FUT * VEG) + w] = p;
        xdec[b * XK_SMALL + w] = p;
    }
    if (threadIdx.x < WEA && wf_next)
        xdec[b * XK_SMALL + VEG + threadIdx.x] = wf_next[b * (T_FUT * WEA) + threadIdx.x];
}

// ---------------------------------------------------------------------------
// Host launcher (graph-capturable: kernel launches only)
// ---------------------------------------------------------------------------
extern "C" void kernel_launch(void* const* d_in, const int* in_sizes, int n_in,
                              void* d_out, int out_size) {
    const float* veg   = (const float*)d_in[0];
    const float* wh    = (const float*)d_in[1];
    const float* wf    = (const float*)d_in[2];
    const float* Wih0  = (const float*)d_in[3];
    const float* Whh0  = (const float*)d_in[4];
    const float* b0    = (const float*)d_in[5];
    const float* Wih1  = (const float*)d_in[6];
    const float* Whh1  = (const float*)d_in[7];
    const float* b1    = (const float*)d_in[8];
    const float* headW = (const float*)d_in[9];
    const float* headb = (const float*)d_in[10];
    float* out = (float*)d_out;

    float *xhist, *y0, *zero, *c0, *c1, *h1a, *h1b, *h0a, *h0b, *pred, *xdec;
    cudaGetSymbolAddress((void**)&xhist, g_xhist);
    cudaGetSymbolAddress((void**)&y0,    g_y0);
    cudaGetSymbolAddress((void**)&zero,  g_zero);
    cudaGetSymbolAddress((void**)&c0,    g_c0);
    cudaGetSymbolAddress((void**)&c1,    g_c1);
    cudaGetSymbolAddress((void**)&h1a,   g_h1a);
    cudaGetSymbolAddress((void**)&h1b,   g_h1b);
    cudaGetSymbolAddress((void**)&h0a,   g_h0a);
    cudaGetSymbolAddress((void**)&h0b,   g_h0b);
    cudaGetSymbolAddress((void**)&pred,  g_pred);
    cudaGetSymbolAddress((void**)&xdec,  g_xdec);

    prep_kernel<<<T_HIST, NB>>>(veg, wh, wf, xhist, pred, xdec);
    zero_kernel<<<(HB + 511) / 512, 512>>>(zero, c0, c1);

    dim3 cgrid(4, 32), cblk(256);

    // encoder layer 0 : x = xhist[t] (K=12), h chain through y0 slices
    for (int t = 0; t < T_HIST; t++) {
        const float* hp = (t == 0) ? zero : (y0 + (t - 1) * HB);
        cell_kernel<false><<<cgrid, cblk>>>(xhist + t * NB * XK_SMALL, hp, c0,
                                            y0 + t * HB, Wih0, Whh0, b0);
    }
    // encoder layer 1 : x = y0[t] (K=512), h ping-pong
    float* H1[2] = {h1a, h1b};
    for (int t = 0; t < T_HIST; t++) {
        const float* hp = (t == 0) ? zero : H1[(t + 1) & 1];
        cell_kernel<true><<<cgrid, cblk>>>(y0 + t * HB, hp, c1, H1[t & 1],
                                           Wih1, Whh1, b1);
    }
    // decoder
    float* H0[2] = {h0a, h0b};
    for (int t = 0; t < T_FUT; t++) {
        const float* hp0 = (t == 0) ? (y0 + (T_HIST - 1) * HB) : H0[(t + 1) & 1];
        cell_kernel<false><<<cgrid, cblk>>>(xdec, hp0, c0, H0[t & 1],
                                            Wih0, Whh0, b0);
        const float* hp1 = H1[(t + 1) & 1];
        cell_kernel<true><<<cgrid, cblk>>>(H0[t & 1], hp1, c1, H1[t & 1],
                                           Wih1, Whh1, b1);
        const float* wfn = (t < T_FUT - 1) ? (wf + (t + 1) * WEA) : nullptr;
        head_kernel<<<NB, 128>>>(H1[t & 1], headW, headb, pred,
                                 out + t * VEG, wfn, xdec);
    }
}

// round 3
// speedup vs baseline: 2.2642x; 2.2642x over previous
#include <cuda_runtime.h>
#include <cuda_bf16.h>
#include <cstdint>
#include <math.h>

// ---------------------------------------------------------------------------
// Problem constants
// ---------------------------------------------------------------------------
#define VEG 4
#define WEA 8
#define HID 512
#define NB  256
#define T_HIST 150
#define T_FUT  50
#define HB (NB * HID)
#define XPW 64            // padded x width (12 real + 52 zeros)
#define GROW 2048         // gate rows (4*HID)

// ---------------------------------------------------------------------------
// Device scratch (static only)
// ---------------------------------------------------------------------------
__device__ __nv_bfloat16 g_xph[T_HIST * NB * XPW];
__device__ __nv_bfloat16 g_xpl[T_HIST * NB * XPW];
__device__ __nv_bfloat16 g_xdh[NB * XPW];
__device__ __nv_bfloat16 g_xdl[NB * XPW];
__device__ float g_pred[NB * VEG];
__device__ __nv_bfloat16 g_y0h[T_HIST * HB];   // layer0 outputs hi (h-chain)
__device__ __nv_bfloat16 g_y0l[T_HIST * HB];
__device__ __nv_bfloat16 g_zb[HB];             // bf16 zeros
__device__ float g_c0[HB];
__device__ float g_c1[HB];
__device__ __nv_bfloat16 g_h1h[2 * HB], g_h1l[2 * HB];
__device__ __nv_bfloat16 g_h0h[2 * HB], g_h0l[2 * HB];
__device__ float g_h1f[HB];
__device__ float g_h0f[HB];                    // sink for layer0 fp32 h
// reordered (row = u*4+g) hi/lo weights
__device__ __nv_bfloat16 g_w0h[GROW * HID], g_w0l[GROW * HID];        // Whh0
__device__ __nv_bfloat16 g_w1hh_h[GROW * HID], g_w1hh_l[GROW * HID];  // Whh1
__device__ __nv_bfloat16 g_w1ih_h[GROW * HID], g_w1ih_l[GROW * HID];  // Wih1
__device__ __nv_bfloat16 g_wx0h[GROW * XPW], g_wx0l[GROW * XPW];      // Wih0 padded
__device__ float g_br0[GROW], g_br1[GROW];

// ---------------------------------------------------------------------------
// Portable PTX helpers (sm_80+ only — this toolchain rejects sm_100a features)
// ---------------------------------------------------------------------------
__device__ __forceinline__ uint32_t smem_u32(const void* p) {
    uint32_t a;
    asm("{ .reg .u64 t; cvta.to.shared.u64 t, %1; cvt.u32.u64 %0, t; }"
        : "=r"(a) : "l"(p));
    return a;
}
#define CP_ASYNC16(dst, src) \
    asm volatile("cp.async.cg.shared.global [%0], [%1], 16;" \
                 :: "r"(dst), "l"(src) : "memory")
#define CP_COMMIT() asm volatile("cp.async.commit_group;" ::: "memory")
#define CP_WAIT1()  asm volatile("cp.async.wait_group 1;" ::: "memory")
#define CP_WAIT0()  asm volatile("cp.async.wait_group 0;" ::: "memory")

#define LDM4(r, addr) \
    asm volatile("ldmatrix.sync.aligned.m8n8.x4.shared.b16 {%0,%1,%2,%3}, [%4];" \
                 : "=r"((r)[0]), "=r"((r)[1]), "=r"((r)[2]), "=r"((r)[3]) \
                 : "r"(addr))

#define MMA16816(d, a, b0, b1) \
    asm volatile( \
        "mma.sync.aligned.m16n8k16.row.col.f32.bf16.bf16.f32 " \
        "{%0,%1,%2,%3}, {%4,%5,%6,%7}, {%8,%9}, {%0,%1,%2,%3};" \
        : "+f"((d)[0]), "+f"((d)[1]), "+f"((d)[2]), "+f"((d)[3]) \
        : "r"((a)[0]), "r"((a)[1]), "r"((a)[2]), "r"((a)[3]), \
          "r"(b0), "r"(b1))

// ---------------------------------------------------------------------------
// SMEM layout
// ---------------------------------------------------------------------------
#define SM_STRIDE 72                       // bf16 elems/row (144B, conflict-free)
#define TILE_B (64 * SM_STRIDE * 2)        // 9216
#define STAGE_B (4 * TILE_B)               // 36864: Ah, Al, Bh, Bl
#define OFF_AH 0
#define OFF_AL (1 * TILE_B)
#define OFF_BH (2 * TILE_B)
#define OFF_BL (3 * TILE_B)
#define CS_STRIDE 68                       // fp32 C tile row stride (16B-aligned)
#define OFF_BIAS (2 * STAGE_B)             // 73728
#define SMEM_TOTAL (OFF_BIAS + 64 * 4 + 16)

// ---------------------------------------------------------------------------
// Math helpers
// ---------------------------------------------------------------------------
__device__ __forceinline__ float sigmoidf_(float x) { return 1.0f / (1.0f + __expf(-x)); }
__device__ __forceinline__ float tanhf_(float x)    { return 2.0f / (1.0f + __expf(-2.0f * x)) - 1.0f; }
__device__ __forceinline__ void split2(float x, __nv_bfloat16& h, __nv_bfloat16& l) {
    h = __float2bfloat16(x);
    l = __float2bfloat16(x - __bfloat162float(h));
}

// ---------------------------------------------------------------------------
// prep: smoothing + padded-x hi/lo for encoder; decoder init at t=149
// ---------------------------------------------------------------------------
__global__ void prep_kernel(const float* __restrict__ veg,
                            const float* __restrict__ wh,
                            const float* __restrict__ wf,
                            __nv_bfloat16* __restrict__ xph,
                            __nv_bfloat16* __restrict__ xpl,
                            __nv_bfloat16* __restrict__ xdh,
                            __nv_bfloat16* __restrict__ xdl,
                            float* __restrict__ pred) {
    int b = threadIdx.x;
    int t = blockIdx.x;
    const int base = (t * NB + b) * XPW;
    float vs[VEG];
#pragma unroll
    for (int v = 0; v < VEG; v++) {
        float val = veg[b * (T_HIST * VEG) + t * VEG + v];
        float s = 0.f;
#pragma unroll
        for (int dt = -2; dt <= 2; dt++) {
            int tt = t + dt;
            if (tt >= 0 && tt < T_HIST) {
                float u = veg[b * (T_HIST * VEG) + tt * VEG + v];
                if (!isnan(u)) s += u;
            }
        }
        float sm = s * 0.2f;
        float outv = isnan(val) ? sm : val;
        if (isnan(outv)) outv = 0.f;
        vs[v] = outv;
        __nv_bfloat16 hh, ll; split2(outv, hh, ll);
        xph[base + v] = hh; xpl[base + v] = ll;
    }
#pragma unroll
    for (int k = 0; k < WEA; k++) {
        float w = wh[b * (T_HIST * WEA) + t * WEA + k];
        __nv_bfloat16 hh, ll; split2(w, hh, ll);
        xph[base + VEG + k] = hh; xpl[base + VEG + k] = ll;
    }
    __nv_bfloat16 z = __float2bfloat16(0.f);
    for (int c = VEG + WEA; c < XPW; c++) { xph[base + c] = z; xpl[base + c] = z; }

    if (t == T_HIST - 1) {
        int db = b * XPW;
#pragma unroll
        for (int v = 0; v < VEG; v++) {
            pred[b * VEG + v] = vs[v];
            __nv_bfloat16 hh, ll; split2(vs[v], hh, ll);
            xdh[db + v] = hh; xdl[db + v] = ll;
        }
#pragma unroll
        for (int k = 0; k < WEA; k++) {
            float w = wf[b * (T_FUT * WEA) + k];
            __nv_bfloat16 hh, ll; split2(w, hh, ll);
            xdh[db + VEG + k] = hh; xdl[db + VEG + k] = ll;
        }
        for (int c = VEG + WEA; c < XPW; c++) { xdh[db + c] = z; xdl[db + c] = z; }
    }
}

// ---------------------------------------------------------------------------
// weight prep: reorder rows to u*4+g, split hi/lo, pad Wih0 to 64 cols
// ---------------------------------------------------------------------------
__global__ void wprep_kernel(const float* __restrict__ Wih0, const float* __restrict__ Whh0,
                             const float* __restrict__ b0,   const float* __restrict__ Wih1,
                             const float* __restrict__ Whh1, const float* __restrict__ b1,
                             __nv_bfloat16* w0h, __nv_bfloat16* w0l,
                             __nv_bfloat16* w1hhh, __nv_bfloat16* w1hhl,
                             __nv_bfloat16* w1ihh, __nv_bfloat16* w1ihl,
                             __nv_bfloat16* wx0h, __nv_bfloat16* wx0l,
                             float* br0, float* br1) {
    int rn = blockIdx.x;                       // new row
    int orig = (rn & 3) * HID + (rn >> 2);     // g*512 + u
    for (int c = threadIdx.x; c < HID; c += blockDim.x) {
        __nv_bfloat16 hh, ll;
        split2(Whh0[orig * HID + c], hh, ll);
        w0h[rn * HID + c] = hh; w0l[rn * HID + c] = ll;
        split2(Whh1[orig * HID + c], hh, ll);
        w1hhh[rn * HID + c] = hh; w1hhl[rn * HID + c] = ll;
        split2(Wih1[orig * HID + c], hh, ll);
        w1ihh[rn * HID + c] = hh; w1ihl[rn * HID + c] = ll;
    }
    if (threadIdx.x < XPW) {
        int c = threadIdx.x;
        float v = (c < VEG + WEA) ? Wih0[orig * (VEG + WEA) + c] : 0.f;
        __nv_bfloat16 hh, ll; split2(v, hh, ll);
        wx0h[rn * XPW + c] = hh; wx0l[rn * XPW + c] = ll;
    }
    if (threadIdx.x == 0) { br0[rn] = b0[orig]; br1[rn] = b1[orig]; }
}

__global__ void zero_kernel(float* __restrict__ c0, float* __restrict__ c1,
                            __nv_bfloat16* __restrict__ zb) {
    int i = blockIdx.x * blockDim.x + threadIdx.x;
    if (i < HB) { c0[i] = 0.f; c1[i] = 0.f; zb[i] = __float2bfloat16(0.f); }
}

// ---------------------------------------------------------------------------
// Fused LSTM cell step on legacy HMMA (bf16 hi/lo 3-pass, fp32-accurate)
//   D[64x64] tile of [h;x] @ [Wh;Wx]^T, reordered gate cols (u*4+g)
// grid (4 Mtiles, 32 unit-tiles) = 128 CTAs, 256 threads, cp.async pipeline
// ---------------------------------------------------------------------------
__global__ void __launch_bounds__(256, 1)
cell_mma(const __nv_bfloat16* __restrict__ AhH, const __nv_bfloat16* __restrict__ AhL,
         const __nv_bfloat16* __restrict__ BhH, const __nv_bfloat16* __restrict__ BhL,
         const __nv_bfloat16* __restrict__ AxH, const __nv_bfloat16* __restrict__ AxL,
         const __nv_bfloat16* __restrict__ BxH, const __nv_bfloat16* __restrict__ BxL,
         int ncx, int ldx,
         const float* __restrict__ biasr,
         float* __restrict__ c, float* __restrict__ hf,
         __nv_bfloat16* __restrict__ hhi, __nv_bfloat16* __restrict__ hlo) {
    extern __shared__ __align__(16) char smem[];
    const uint32_t sbase = smem_u32(smem);
    const int tid = threadIdx.x;
    const int warp = tid >> 5;
    const int lane = tid & 31;
    const int m0 = blockIdx.x * 64;
    const int n0 = blockIdx.y * 64;   // reordered weight row base
    const int u0 = blockIdx.y * 16;   // unit base
    const int wm = warp >> 2;         // 0..1
    const int wn = warp & 3;          // 0..3

    if (tid < 64)
        *reinterpret_cast<float*>(smem + OFF_BIAS + tid * 4) = biasr[n0 + tid];

    float cfr[2][2][4];
#pragma unroll
    for (int mi = 0; mi < 2; mi++)
#pragma unroll
        for (int nj = 0; nj < 2; nj++)
#pragma unroll
            for (int r = 0; r < 4; r++) cfr[mi][nj][r] = 0.f;

    const int NC = 8 + ncx;

    // ---- chunk prefetch via cp.async (Ah, Al, Bh, Bl : 64x64 bf16 each) ----
    auto prefetch = [&](int ch, int s) {
        const __nv_bfloat16 *aH, *aL, *bH, *bL;
        int lda, k0;
        if (ch < 8) { aH = AhH; aL = AhL; bH = BhH; bL = BhL; lda = HID; k0 = ch * 64; }
        else        { aH = AxH; aL = AxL; bH = BxH; bL = BxL; lda = ldx; k0 = (ch - 8) * 64; }
        const uint32_t st = sbase + s * STAGE_B;
#pragma unroll
        for (int i = 0; i < 2; i++) {
            int idx = tid + i * 256;
            int r = idx >> 3, q = idx & 7;
            uint32_t off = r * (SM_STRIDE * 2) + q * 16;
            long ao = (long)(m0 + r) * lda + k0 + q * 8;
            long bo = (long)(n0 + r) * lda + k0 + q * 8;
            CP_ASYNC16(st + OFF_AH + off, aH + ao);
            CP_ASYNC16(st + OFF_AL + off, aL + ao);
            CP_ASYNC16(st + OFF_BH + off, bH + bo);
            CP_ASYNC16(st + OFF_BL + off, bL + bo);
        }
    };

    prefetch(0, 0);
    CP_COMMIT();

    for (int ch = 0; ch < NC; ch++) {
        const int s = ch & 1;
        if (ch + 1 < NC) { prefetch(ch + 1, 1 - s); CP_COMMIT(); CP_WAIT1(); }
        else             { CP_WAIT0(); }
        __syncthreads();

        const uint32_t base = sbase + s * STAGE_B;
#pragma unroll
        for (int kk = 0; kk < 64; kk += 16) {
            uint32_t ah[2][4], al[2][4], bh[2][2], bl[2][2];
#pragma unroll
            for (int mi = 0; mi < 2; mi++) {
                uint32_t roff =
                    (uint32_t)((wm * 32 + mi * 16 + (lane & 15)) * (SM_STRIDE * 2) +
                               (kk + (lane >> 4) * 8) * 2);
                LDM4(ah[mi], base + OFF_AH + roff);
                LDM4(al[mi], base + OFF_AL + roff);
            }
            {
                uint32_t roff =
                    (uint32_t)((wn * 16 + (lane & 15)) * (SM_STRIDE * 2) +
                               (kk + (lane >> 4) * 8) * 2);
                uint32_t rb[4], rl[4];
                LDM4(rb, base + OFF_BH + roff);
                LDM4(rl, base + OFF_BL + roff);
                bh[0][0] = rb[0]; bh[0][1] = rb[2];
                bh[1][0] = rb[1]; bh[1][1] = rb[3];
                bl[0][0] = rl[0]; bl[0][1] = rl[2];
                bl[1][0] = rl[1]; bl[1][1] = rl[3];
            }
#pragma unroll
            for (int mi = 0; mi < 2; mi++)
#pragma unroll
                for (int nj = 0; nj < 2; nj++) {
                    MMA16816(cfr[mi][nj], ah[mi], bh[nj][0], bh[nj][1]);
                    MMA16816(cfr[mi][nj], ah[mi], bl[nj][0], bl[nj][1]);
                    MMA16816(cfr[mi][nj], al[mi], bh[nj][0], bh[nj][1]);
                }
        }
        __syncthreads();
    }

    // ---- epilogue: fragments -> smem C tile -> gate math ----
    float* Cs = reinterpret_cast<float*>(smem);   // 64 x CS_STRIDE fp32
#pragma unroll
    for (int mi = 0; mi < 2; mi++)
#pragma unroll
        for (int nj = 0; nj < 2; nj++) {
            int r = wm * 32 + mi * 16 + (lane >> 2);
            int col = wn * 16 + nj * 8 + (lane & 3) * 2;
            Cs[r * CS_STRIDE + col]           = cfr[mi][nj][0];
            Cs[r * CS_STRIDE + col + 1]       = cfr[mi][nj][1];
            Cs[(r + 8) * CS_STRIDE + col]     = cfr[mi][nj][2];
            Cs[(r + 8) * CS_STRIDE + col + 1] = cfr[mi][nj][3];
        }
    __syncthreads();

    const float* Bs = reinterpret_cast<const float*>(smem + OFF_BIAS);
#pragma unroll
    for (int k = 0; k < 4; k++) {
        int id = tid + k * 256;
        int u = id & 15, bb = id >> 4;
        float4 g4 = *reinterpret_cast<const float4*>(&Cs[bb * CS_STRIDE + u * 4]);
        float gi = sigmoidf_(g4.x + Bs[u * 4 + 0]);
        float gf = sigmoidf_(g4.y + Bs[u * 4 + 1]);
        float gg = tanhf_   (g4.z + Bs[u * 4 + 2]);
        float go = sigmoidf_(g4.w + Bs[u * 4 + 3]);
        int gidx = (m0 + bb) * HID + u0 + u;
        float cn = gf * c[gidx] + gi * gg;
        c[gidx] = cn;
        float hv = go * tanhf_(cn);
        hf[gidx] = hv;
        __nv_bfloat16 hh, ll; split2(hv, hh, ll);
        hhi[gidx] = hh; hlo[gidx] = ll;
    }
}

// ---------------------------------------------------------------------------
// head: pred += h1 @ headW^T + headb ; write output[t]; build next decoder x
// ---------------------------------------------------------------------------
__global__ void head_kernel(const float* __restrict__ h1,
                            const float* __restrict__ headW,
                            const float* __restrict__ headb,
                            float* __restrict__ pred,
                            float* __restrict__ out_t,
                            const float* __restrict__ wf_next,
                            __nv_bfloat16* __restrict__ xdh,
                            __nv_bfloat16* __restrict__ xdl) {
    int b = blockIdx.x;
    int w = threadIdx.x >> 5;
    int lane = threadIdx.x & 31;
    const float* hr = &h1[b * HID];
    const float* wr = &headW[w * HID];
    float s = 0.f;
    for (int k = lane; k < HID; k += 32) s += hr[k] * wr[k];
#pragma unroll
    for (int o = 16; o; o >>= 1) s += __shfl_down_sync(0xffffffffu, s, o);
    if (lane == 0) {
        float p = pred[b * VEG + w] + s + headb[w];
        pred[b * VEG + w] = p;
        out_t[b * (T_FUT * VEG) + w] = p;
        __nv_bfloat16 hh, ll; split2(p, hh, ll);
        xdh[b * XPW + w] = hh; xdl[b * XPW + w] = ll;
    }
    if (threadIdx.x < WEA && wf_next) {
        float v = wf_next[b * (T_FUT * WEA) + threadIdx.x];
        __nv_bfloat16 hh, ll; split2(v, hh, ll);
        xdh[b * XPW + VEG + threadIdx.x] = hh;
        xdl[b * XPW + VEG + threadIdx.x] = ll;
    }
}

// ---------------------------------------------------------------------------
// Host launcher
// ---------------------------------------------------------------------------
extern "C" void kernel_launch(void* const* d_in, const int* in_sizes, int n_in,
                              void* d_out, int out_size) {
    const float* veg   = (const float*)d_in[0];
    const float* wh    = (const float*)d_in[1];
    const float* wf    = (const float*)d_in[2];
    const float* Wih0  = (const float*)d_in[3];
    const float* Whh0  = (const float*)d_in[4];
    const float* b0    = (const float*)d_in[5];
    const float* Wih1  = (const float*)d_in[6];
    const float* Whh1  = (const float*)d_in[7];
    const float* b1    = (const float*)d_in[8];
    const float* headW = (const float*)d_in[9];
    const float* headb = (const float*)d_in[10];
    float* out = (float*)d_out;

    __nv_bfloat16 *xph, *xpl, *xdh, *xdl, *y0h, *y0l, *zb;
    __nv_bfloat16 *h1h, *h1l, *h0h, *h0l;
    __nv_bfloat16 *w0h, *w0l, *w1hhh, *w1hhl, *w1ihh, *w1ihl, *wx0h, *wx0l;
    float *pred, *c0, *c1, *h1f, *h0f, *br0, *br1;
    cudaGetSymbolAddress((void**)&xph,   g_xph);
    cudaGetSymbolAddress((void**)&xpl,   g_xpl);
    cudaGetSymbolAddress((void**)&xdh,   g_xdh);
    cudaGetSymbolAddress((void**)&xdl,   g_xdl);
    cudaGetSymbolAddress((void**)&pred,  g_pred);
    cudaGetSymbolAddress((void**)&y0h,   g_y0h);
    cudaGetSymbolAddress((void**)&y0l,   g_y0l);
    cudaGetSymbolAddress((void**)&zb,    g_zb);
    cudaGetSymbolAddress((void**)&c0,    g_c0);
    cudaGetSymbolAddress((void**)&c1,    g_c1);
    cudaGetSymbolAddress((void**)&h1h,   g_h1h);
    cudaGetSymbolAddress((void**)&h1l,   g_h1l);
    cudaGetSymbolAddress((void**)&h0h,   g_h0h);
    cudaGetSymbolAddress((void**)&h0l,   g_h0l);
    cudaGetSymbolAddress((void**)&h1f,   g_h1f);
    cudaGetSymbolAddress((void**)&h0f,   g_h0f);
    cudaGetSymbolAddress((void**)&w0h,   g_w0h);
    cudaGetSymbolAddress((void**)&w0l,   g_w0l);
    cudaGetSymbolAddress((void**)&w1hhh, g_w1hh_h);
    cudaGetSymbolAddress((void**)&w1hhl, g_w1hh_l);
    cudaGetSymbolAddress((void**)&w1ihh, g_w1ih_h);
    cudaGetSymbolAddress((void**)&w1ihl, g_w1ih_l);
    cudaGetSymbolAddress((void**)&wx0h,  g_wx0h);
    cudaGetSymbolAddress((void**)&wx0l,  g_wx0l);
    cudaGetSymbolAddress((void**)&br0,   g_br0);
    cudaGetSymbolAddress((void**)&br1,   g_br1);

    cudaFuncSetAttribute(cell_mma, cudaFuncAttributeMaxDynamicSharedMemorySize,
                         SMEM_TOTAL);

    prep_kernel<<<T_HIST, NB>>>(veg, wh, wf, xph, xpl, xdh, xdl, pred);
    wprep_kernel<<<GROW, 128>>>(Wih0, Whh0, b0, Wih1, Whh1, b1,
                                w0h, w0l, w1hhh, w1hhl, w1ihh, w1ihl,
                                wx0h, wx0l, br0, br1);
    zero_kernel<<<(HB + 255) / 256, 256>>>(c0, c1, zb);

    dim3 grid(4, 32), blk(256);

    // encoder layer 0: h chain through y0 hi/lo slices; x = padded hist (1 chunk)
    for (int t = 0; t < T_HIST; t++) {
        const __nv_bfloat16* hpH = (t == 0) ? zb : (y0h + (size_t)(t - 1) * HB);
        const __nv_bfloat16* hpL = (t == 0) ? zb : (y0l + (size_t)(t - 1) * HB);
        cell_mma<<<grid, blk, SMEM_TOTAL>>>(
            hpH, hpL, w0h, w0l,
            xph + (size_t)t * NB * XPW, xpl + (size_t)t * NB * XPW, wx0h, wx0l,
            1, XPW, br0, c0, h0f, y0h + (size_t)t * HB, y0l + (size_t)t * HB);
    }
    // encoder layer 1: x = y0[t] (8 chunks)
    for (int t = 0; t < T_HIST; t++) {
        const __nv_bfloat16* hpH = (t == 0) ? zb : (h1h + ((t + 1) & 1) * HB);
        const __nv_bfloat16* hpL = (t == 0) ? zb : (h1l + ((t + 1) & 1) * HB);
        cell_mma<<<grid, blk, SMEM_TOTAL>>>(
            hpH, hpL, w1hhh, w1hhl,
            y0h + (size_t)t * HB, y0l + (size_t)t * HB, w1ihh, w1ihl,
            8, HID, br1, c1, h1f, h1h + (t & 1) * HB, h1l + (t & 1) * HB);
    }
    // decoder
    for (int t = 0; t < T_FUT; t++) {
        const __nv_bfloat16* hpH = (t == 0) ? (y0h + (size_t)(T_HIST - 1) * HB)
                                            : (h0h + ((t + 1) & 1) * HB);
        const __nv_bfloat16* hpL = (t == 0) ? (y0l + (size_t)(T_HIST - 1) * HB)
                                            : (h0l + ((t + 1) & 1) * HB);
        cell_mma<<<grid, blk, SMEM_TOTAL>>>(
            hpH, hpL, w0h, w0l, xdh, xdl, wx0h, wx0l,
            1, XPW, br0, c0, h0f, h0h + (t & 1) * HB, h0l + (t & 1) * HB);
        cell_mma<<<grid, blk, SMEM_TOTAL>>>(
            h1h + ((t + 1) & 1) * HB, h1l + ((t + 1) & 1) * HB, w1hhh, w1hhl,
            h0h + (t & 1) * HB, h0l + (t & 1) * HB, w1ihh, w1ihl,
            8, HID, br1, c1, h1f, h1h + (t & 1) * HB, h1l + (t & 1) * HB);
        const float* wfn = (t < T_FUT - 1) ? (wf + (t + 1) * WEA) : nullptr;
        head_kernel<<<NB, 128>>>(h1f, headW, headb, pred,
                                 out + t * VEG, wfn, xdh, xdl);
    }
}

// round 7
// speedup vs baseline: 2.7299x; 1.2057x over previous
#include <cuda_runtime.h>
#include <cuda_bf16.h>
#include <cstdint>
#include <math.h>

// ---------------------------------------------------------------------------
// Problem constants
// ---------------------------------------------------------------------------
#define VEG 4
#define WEA 8
#define HID 512
#define NB  256
#define T_HIST 150
#define T_FUT  50
#define HB (NB * HID)
#define XPW 64            // padded x width (12 real + 52 zeros)
#define GROW 2048         // gate rows (4*HID)

// ---------------------------------------------------------------------------
// Device scratch (static only)
// ---------------------------------------------------------------------------
__device__ __nv_bfloat16 g_xph[T_HIST * NB * XPW];
__device__ __nv_bfloat16 g_xpl[T_HIST * NB * XPW];
__device__ __nv_bfloat16 g_xdh[NB * XPW];
__device__ __nv_bfloat16 g_xdl[NB * XPW];
__device__ float g_pred[NB * VEG];
__device__ __nv_bfloat16 g_y0h[T_HIST * HB];   // layer0 outputs hi (h-chain)
__device__ __nv_bfloat16 g_y0l[T_HIST * HB];
__device__ __nv_bfloat16 g_zb[HB];             // bf16 zeros
__device__ float g_c0[HB];
__device__ float g_c1[HB];
__device__ __nv_bfloat16 g_h1h[2 * HB], g_h1l[2 * HB];
__device__ __nv_bfloat16 g_h0h[2 * HB], g_h0l[2 * HB];
__device__ float g_h1f[HB];
__device__ float g_h0f[HB];                    // sink for layer0 fp32 h
// reordered (row = u*4+g) hi/lo weights
__device__ __nv_bfloat16 g_w0h[GROW * HID], g_w0l[GROW * HID];        // Whh0
__device__ __nv_bfloat16 g_w1hh_h[GROW * HID], g_w1hh_l[GROW * HID];  // Whh1
__device__ __nv_bfloat16 g_w1ih_h[GROW * HID], g_w1ih_l[GROW * HID];  // Wih1
__device__ __nv_bfloat16 g_wx0h[GROW * XPW], g_wx0l[GROW * XPW];      // Wih0 padded
__device__ float g_br0[GROW], g_br1[GROW];

// ---------------------------------------------------------------------------
// Portable PTX helpers (sm_80+ only — this toolchain rejects sm_100a features)
// ---------------------------------------------------------------------------
__device__ __forceinline__ uint32_t smem_u32(const void* p) {
    uint32_t a;
    asm("{ .reg .u64 t; cvta.to.shared.u64 t, %1; cvt.u32.u64 %0, t; }"
        : "=r"(a) : "l"(p));
    return a;
}
#define CP_ASYNC16(dst, src) \
    asm volatile("cp.async.cg.shared.global [%0], [%1], 16;" \
                 :: "r"(dst), "l"(src) : "memory")
#define CP_COMMIT() asm volatile("cp.async.commit_group;" ::: "memory")
#define CP_WAIT1()  asm volatile("cp.async.wait_group 1;" ::: "memory")
#define CP_WAIT0()  asm volatile("cp.async.wait_group 0;" ::: "memory")

#define LDM4(r, addr) \
    asm volatile("ldmatrix.sync.aligned.m8n8.x4.shared.b16 {%0,%1,%2,%3}, [%4];" \
                 : "=r"((r)[0]), "=r"((r)[1]), "=r"((r)[2]), "=r"((r)[3]) \
                 : "r"(addr))

#define MMA16816(d, a, b0, b1) \
    asm volatile( \
        "mma.sync.aligned.m16n8k16.row.col.f32.bf16.bf16.f32 " \
        "{%0,%1,%2,%3}, {%4,%5,%6,%7}, {%8,%9}, {%0,%1,%2,%3};" \
        : "+f"((d)[0]), "+f"((d)[1]), "+f"((d)[2]), "+f"((d)[3]) \
        : "r"((a)[0]), "r"((a)[1]), "r"((a)[2]), "r"((a)[3]), \
          "r"(b0), "r"(b1))

// ---------------------------------------------------------------------------
// SMEM layout — 3-stage pipeline
// ---------------------------------------------------------------------------
#define SM_STRIDE 72                       // bf16 elems/row (144B, conflict-free)
#define TILE_B (64 * SM_STRIDE * 2)        // 9216
#define STAGE_B (4 * TILE_B)               // 36864: Ah, Al, Bh, Bl
#define NSTAGE 3
#define OFF_AH 0
#define OFF_AL (1 * TILE_B)
#define OFF_BH (2 * TILE_B)
#define OFF_BL (3 * TILE_B)
#define CS_STRIDE 68                       // fp32 C tile row stride (16B-aligned)
#define OFF_BIAS (NSTAGE * STAGE_B)        // 110592
#define SMEM_TOTAL (OFF_BIAS + 64 * 4 + 16)

// ---------------------------------------------------------------------------
// Math helpers
// ---------------------------------------------------------------------------
__device__ __forceinline__ float sigmoidf_(float x) { return 1.0f / (1.0f + __expf(-x)); }
__device__ __forceinline__ float tanhf_(float x)    { return 2.0f / (1.0f + __expf(-2.0f * x)) - 1.0f; }
__device__ __forceinline__ void split2(float x, __nv_bfloat16& h, __nv_bfloat16& l) {
    h = __float2bfloat16(x);
    l = __float2bfloat16(x - __bfloat162float(h));
}

// ---------------------------------------------------------------------------
// prep: smoothing + padded-x hi/lo for encoder; decoder init at t=149
// ---------------------------------------------------------------------------
__global__ void prep_kernel(const float* __restrict__ veg,
                            const float* __restrict__ wh,
                            const float* __restrict__ wf,
                            __nv_bfloat16* __restrict__ xph,
                            __nv_bfloat16* __restrict__ xpl,
                            __nv_bfloat16* __restrict__ xdh,
                            __nv_bfloat16* __restrict__ xdl,
                            float* __restrict__ pred) {
    int b = threadIdx.x;
    int t = blockIdx.x;
    const int base = (t * NB + b) * XPW;
    float vs[VEG];
#pragma unroll
    for (int v = 0; v < VEG; v++) {
        float val = veg[b * (T_HIST * VEG) + t * VEG + v];
        float s = 0.f;
#pragma unroll
        for (int dt = -2; dt <= 2; dt++) {
            int tt = t + dt;
            if (tt >= 0 && tt < T_HIST) {
                float u = veg[b * (T_HIST * VEG) + tt * VEG + v];
                if (!isnan(u)) s += u;
            }
        }
        float sm = s * 0.2f;
        float outv = isnan(val) ? sm : val;
        if (isnan(outv)) outv = 0.f;
        vs[v] = outv;
        __nv_bfloat16 hh, ll; split2(outv, hh, ll);
        xph[base + v] = hh; xpl[base + v] = ll;
    }
#pragma unroll
    for (int k = 0; k < WEA; k++) {
        float w = wh[b * (T_HIST * WEA) + t * WEA + k];
        __nv_bfloat16 hh, ll; split2(w, hh, ll);
        xph[base + VEG + k] = hh; xpl[base + VEG + k] = ll;
    }
    __nv_bfloat16 z = __float2bfloat16(0.f);
    for (int c = VEG + WEA; c < XPW; c++) { xph[base + c] = z; xpl[base + c] = z; }

    if (t == T_HIST - 1) {
        int db = b * XPW;
#pragma unroll
        for (int v = 0; v < VEG; v++) {
            pred[b * VEG + v] = vs[v];
            __nv_bfloat16 hh, ll; split2(vs[v], hh, ll);
            xdh[db + v] = hh; xdl[db + v] = ll;
        }
#pragma unroll
        for (int k = 0; k < WEA; k++) {
            float w = wf[b * (T_FUT * WEA) + k];
            __nv_bfloat16 hh, ll; split2(w, hh, ll);
            xdh[db + VEG + k] = hh; xdl[db + VEG + k] = ll;
        }
        for (int c = VEG + WEA; c < XPW; c++) { xdh[db + c] = z; xdl[db + c] = z; }
    }
}

// ---------------------------------------------------------------------------
// weight prep: reorder rows to u*4+g, split hi/lo, pad Wih0 to 64 cols
// ---------------------------------------------------------------------------
__global__ void wprep_kernel(const float* __restrict__ Wih0, const float* __restrict__ Whh0,
                             const float* __restrict__ b0,   const float* __restrict__ Wih1,
                             const float* __restrict__ Whh1, const float* __restrict__ b1,
                             __nv_bfloat16* w0h, __nv_bfloat16* w0l,
                             __nv_bfloat16* w1hhh, __nv_bfloat16* w1hhl,
                             __nv_bfloat16* w1ihh, __nv_bfloat16* w1ihl,
                             __nv_bfloat16* wx0h, __nv_bfloat16* wx0l,
                             float* br0, float* br1) {
    int rn = blockIdx.x;                       // new row
    int orig = (rn & 3) * HID + (rn >> 2);     // g*512 + u
    for (int c = threadIdx.x; c < HID; c += blockDim.x) {
        __nv_bfloat16 hh, ll;
        split2(Whh0[orig * HID + c], hh, ll);
        w0h[rn * HID + c] = hh; w0l[rn * HID + c] = ll;
        split2(Whh1[orig * HID + c], hh, ll);
        w1hhh[rn * HID + c] = hh; w1hhl[rn * HID + c] = ll;
        split2(Wih1[orig * HID + c], hh, ll);
        w1ihh[rn * HID + c] = hh; w1ihl[rn * HID + c] = ll;
    }
    if (threadIdx.x < XPW) {
        int c = threadIdx.x;
        float v = (c < VEG + WEA) ? Wih0[orig * (VEG + WEA) + c] : 0.f;
        __nv_bfloat16 hh, ll; split2(v, hh, ll);
        wx0h[rn * XPW + c] = hh; wx0l[rn * XPW + c] = ll;
    }
    if (threadIdx.x == 0) { br0[rn] = b0[orig]; br1[rn] = b1[orig]; }
}

__global__ void zero_kernel(float* __restrict__ c0, float* __restrict__ c1,
                            __nv_bfloat16* __restrict__ zb) {
    int i = blockIdx.x * blockDim.x + threadIdx.x;
    if (i < HB) { c0[i] = 0.f; c1[i] = 0.f; zb[i] = __float2bfloat16(0.f); }
}

// ---------------------------------------------------------------------------
// Cell body: one 64(batch)x64(gate) tile of a fused LSTM step on HMMA.
// bf16 hi/lo 3-pass (hi*hi, hi*lo, lo*hi), 3-stage cp.async pipeline,
// dual accumulators, fused gate epilogue.
// ---------------------------------------------------------------------------
__device__ __forceinline__ void cell_body(
    char* smem, int m0, int tileY,
    const __nv_bfloat16* __restrict__ AhH, const __nv_bfloat16* __restrict__ AhL,
    const __nv_bfloat16* __restrict__ BhH, const __nv_bfloat16* __restrict__ BhL,
    const __nv_bfloat16* __restrict__ AxH, const __nv_bfloat16* __restrict__ AxL,
    const __nv_bfloat16* __restrict__ BxH, const __nv_bfloat16* __restrict__ BxL,
    int ncx, int ldx,
    const float* __restrict__ biasr,
    float* __restrict__ c, float* __restrict__ hf,
    __nv_bfloat16* __restrict__ hhi, __nv_bfloat16* __restrict__ hlo) {

    const uint32_t sbase = smem_u32(smem);
    const int tid = threadIdx.x;
    const int warp = tid >> 5;
    const int lane = tid & 31;
    const int n0 = tileY * 64;        // reordered weight row base
    const int u0 = tileY * 16;        // unit base
    const int wm = warp >> 2;         // 0..1
    const int wn = warp & 3;          // 0..3

    if (tid < 64)
        *reinterpret_cast<float*>(smem + OFF_BIAS + tid * 4) = biasr[n0 + tid];

    float cfr[2][2][4];   // hi*hi
    float cfl[2][2][4];   // hi*lo + lo*hi
#pragma unroll
    for (int mi = 0; mi < 2; mi++)
#pragma unroll
        for (int nj = 0; nj < 2; nj++)
#pragma unroll
            for (int r = 0; r < 4; r++) { cfr[mi][nj][r] = 0.f; cfl[mi][nj][r] = 0.f; }

    const int NC = 8 + ncx;

    auto prefetch = [&](int ch) {
        const __nv_bfloat16 *aH, *aL, *bH, *bL;
        int lda, k0;
        if (ch < 8) { aH = AhH; aL = AhL; bH = BhH; bL = BhL; lda = HID; k0 = ch * 64; }
        else        { aH = AxH; aL = AxL; bH = BxH; bL = BxL; lda = ldx; k0 = (ch - 8) * 64; }
        const uint32_t st = sbase + (ch % NSTAGE) * STAGE_B;
#pragma unroll
        for (int i = 0; i < 2; i++) {
            int idx = tid + i * 256;
            int r = idx >> 3, q = idx & 7;
            uint32_t off = r * (SM_STRIDE * 2) + q * 16;
            long ao = (long)(m0 + r) * lda + k0 + q * 8;
            long bo = (long)(n0 + r) * lda + k0 + q * 8;
            CP_ASYNC16(st + OFF_AH + off, aH + ao);
            CP_ASYNC16(st + OFF_AL + off, aL + ao);
            CP_ASYNC16(st + OFF_BH + off, bH + bo);
            CP_ASYNC16(st + OFF_BL + off, bL + bo);
        }
    };

    prefetch(0); CP_COMMIT();
    prefetch(1); CP_COMMIT();

    for (int ch = 0; ch < NC; ch++) {
        if (ch + 1 < NC) CP_WAIT1(); else CP_WAIT0();
        __syncthreads();                    // publishes chunk ch, frees stage (ch+2)%3
        if (ch + 2 < NC) { prefetch(ch + 2); CP_COMMIT(); }

        const uint32_t base = sbase + (ch % NSTAGE) * STAGE_B;
#pragma unroll
        for (int kk = 0; kk < 64; kk += 16) {
            uint32_t ah[2][4], al[2][4], bh[2][2], bl[2][2];
#pragma unroll
            for (int mi = 0; mi < 2; mi++) {
                uint32_t roff =
                    (uint32_t)((wm * 32 + mi * 16 + (lane & 15)) * (SM_STRIDE * 2) +
                               (kk + (lane >> 4) * 8) * 2);
                LDM4(ah[mi], base + OFF_AH + roff);
                LDM4(al[mi], base + OFF_AL + roff);
            }
            {
                uint32_t roff =
                    (uint32_t)((wn * 16 + (lane & 15)) * (SM_STRIDE * 2) +
                               (kk + (lane >> 4) * 8) * 2);
                uint32_t rb[4], rl[4];
                LDM4(rb, base + OFF_BH + roff);
                LDM4(rl, base + OFF_BL + roff);
                bh[0][0] = rb[0]; bh[0][1] = rb[2];
                bh[1][0] = rb[1]; bh[1][1] = rb[3];
                bl[0][0] = rl[0]; bl[0][1] = rl[2];
                bl[1][0] = rl[1]; bl[1][1] = rl[3];
            }
#pragma unroll
            for (int mi = 0; mi < 2; mi++)
#pragma unroll
                for (int nj = 0; nj < 2; nj++) {
                    MMA16816(cfr[mi][nj], ah[mi], bh[nj][0], bh[nj][1]);
                    MMA16816(cfl[mi][nj], ah[mi], bl[nj][0], bl[nj][1]);
                    MMA16816(cfl[mi][nj], al[mi], bh[nj][0], bh[nj][1]);
                }
        }
    }
    __syncthreads();   // all ldmatrix reads done before Cs overwrites stage 0

    // ---- epilogue: fragments -> smem C tile -> gate math ----
    float* Cs = reinterpret_cast<float*>(smem);   // 64 x CS_STRIDE fp32
#pragma unroll
    for (int mi = 0; mi < 2; mi++)
#pragma unroll
        for (int nj = 0; nj < 2; nj++) {
            int r = wm * 32 + mi * 16 + (lane >> 2);
            int col = wn * 16 + nj * 8 + (lane & 3) * 2;
            Cs[r * CS_STRIDE + col]           = cfr[mi][nj][0] + cfl[mi][nj][0];
            Cs[r * CS_STRIDE + col + 1]       = cfr[mi][nj][1] + cfl[mi][nj][1];
            Cs[(r + 8) * CS_STRIDE + col]     = cfr[mi][nj][2] + cfl[mi][nj][2];
            Cs[(r + 8) * CS_STRIDE + col + 1] = cfr[mi][nj][3] + cfl[mi][nj][3];
        }
    __syncthreads();

    const float* Bs = reinterpret_cast<const float*>(smem + OFF_BIAS);
#pragma unroll
    for (int k = 0; k < 4; k++) {
        int id = tid + k * 256;
        int u = id & 15, bb = id >> 4;
        float4 g4 = *reinterpret_cast<const float4*>(&Cs[bb * CS_STRIDE + u * 4]);
        float gi = sigmoidf_(g4.x + Bs[u * 4 + 0]);
        float gf = sigmoidf_(g4.y + Bs[u * 4 + 1]);
        float gg = tanhf_   (g4.z + Bs[u * 4 + 2]);
        float go = sigmoidf_(g4.w + Bs[u * 4 + 3]);
        int gidx = (m0 + bb) * HID + u0 + u;
        float cn = gf * c[gidx] + gi * gg;
        c[gidx] = cn;
        float hv = go * tanhf_(cn);
        hf[gidx] = hv;
        __nv_bfloat16 hh, ll; split2(hv, hh, ll);
        hhi[gidx] = hh; hlo[gidx] = ll;
    }
}

// ---------------------------------------------------------------------------
// Single-cell kernel (decoder + encoder endpoints)
// ---------------------------------------------------------------------------
__global__ void __launch_bounds__(256, 1)
cell_mma(const __nv_bfloat16* __restrict__ AhH, const __nv_bfloat16* __restrict__ AhL,
         const __nv_bfloat16* __restrict__ BhH, const __nv_bfloat16* __restrict__ BhL,
         const __nv_bfloat16* __restrict__ AxH, const __nv_bfloat16* __restrict__ AxL,
         const __nv_bfloat16* __restrict__ BxH, const __nv_bfloat16* __restrict__ BxL,
         int ncx, int ldx,
         const float* __restrict__ biasr,
         float* __restrict__ c, float* __restrict__ hf,
         __nv_bfloat16* __restrict__ hhi, __nv_bfloat16* __restrict__ hlo) {
    extern __shared__ __align__(16) char smem[];
    cell_body(smem, blockIdx.x * 64, blockIdx.y,
              AhH, AhL, BhH, BhL, AxH, AxL, BxH, BxL,
              ncx, ldx, biasr, c, hf, hhi, hlo);
}

// ---------------------------------------------------------------------------
// Merged encoder wavefront step: L1(t) on tiles y<32, L0(t+1) on tiles y>=32.
// Both depend only on data produced at step t — independent within the launch.
// ---------------------------------------------------------------------------
__global__ void __launch_bounds__(256, 1)
enc_step(// L1(t):
         const __nv_bfloat16* __restrict__ h1pH, const __nv_bfloat16* __restrict__ h1pL,
         const __nv_bfloat16* __restrict__ w1hhh, const __nv_bfloat16* __restrict__ w1hhl,
         const __nv_bfloat16* __restrict__ y0tH, const __nv_bfloat16* __restrict__ y0tL,
         const __nv_bfloat16* __restrict__ w1ihh, const __nv_bfloat16* __restrict__ w1ihl,
         const float* __restrict__ br1, float* __restrict__ c1,
         float* __restrict__ h1f,
         __nv_bfloat16* __restrict__ h1oh, __nv_bfloat16* __restrict__ h1ol,
         // L0(t+1):
         const __nv_bfloat16* __restrict__ xnH, const __nv_bfloat16* __restrict__ xnL,
         const __nv_bfloat16* __restrict__ w0h, const __nv_bfloat16* __restrict__ w0l,
         const __nv_bfloat16* __restrict__ wx0h, const __nv_bfloat16* __restrict__ wx0l,
         const float* __restrict__ br0, float* __restrict__ c0,
         float* __restrict__ h0f,
         __nv_bfloat16* __restrict__ y0nH, __nv_bfloat16* __restrict__ y0nL) {
    extern __shared__ __align__(16) char smem[];
    const int m0 = blockIdx.x * 64;
    if (blockIdx.y < 32) {
        // layer 1, step t: A = h1(t-1), X = y0(t)
        cell_body(smem, m0, blockIdx.y,
                  h1pH, h1pL, w1hhh, w1hhl, y0tH, y0tL, w1ihh, w1ihl,
                  8, HID, br1, c1, h1f, h1oh, h1ol);
    } else {
        // layer 0, step t+1: A = y0(t) (h-prev), X = xhist(t+1)
        cell_body(smem, m0, blockIdx.y - 32,
                  y0tH, y0tL, w0h, w0l, xnH, xnL, wx0h, wx0l,
                  1, XPW, br0, c0, h0f, y0nH, y0nL);
    }
}

// ---------------------------------------------------------------------------
// head: pred += h1 @ headW^T + headb ; write output[t]; build next decoder x
// ---------------------------------------------------------------------------
__global__ void head_kernel(const float* __restrict__ h1,
                            const float* __restrict__ headW,
                            const float* __restrict__ headb,
                            float* __restrict__ pred,
                            float* __restrict__ out_t,
                            const float* __restrict__ wf_next,
                            __nv_bfloat16* __restrict__ xdh,
                            __nv_bfloat16* __restrict__ xdl) {
    int b = blockIdx.x;
    int w = threadIdx.x >> 5;
    int lane = threadIdx.x & 31;
    const float* hr = &h1[b * HID];
    const float* wr = &headW[w * HID];
    float s = 0.f;
    for (int k = lane; k < HID; k += 32) s += hr[k] * wr[k];
#pragma unroll
    for (int o = 16; o; o >>= 1) s += __shfl_down_sync(0xffffffffu, s, o);
    if (lane == 0) {
        float p = pred[b * VEG + w] + s + headb[w];
        pred[b * VEG + w] = p;
        out_t[b * (T_FUT * VEG) + w] = p;
        __nv_bfloat16 hh, ll; split2(p, hh, ll);
        xdh[b * XPW + w] = hh; xdl[b * XPW + w] = ll;
    }
    if (threadIdx.x < WEA && wf_next) {
        float v = wf_next[b * (T_FUT * WEA) + threadIdx.x];
        __nv_bfloat16 hh, ll; split2(v, hh, ll);
        xdh[b * XPW + VEG + threadIdx.x] = hh;
        xdl[b * XPW + VEG + threadIdx.x] = ll;
    }
}

// ---------------------------------------------------------------------------
// Host launcher (single stream — graph-capture safe)
// ---------------------------------------------------------------------------
extern "C" void kernel_launch(void* const* d_in, const int* in_sizes, int n_in,
                              void* d_out, int out_size) {
    const float* veg   = (const float*)d_in[0];
    const float* wh    = (const float*)d_in[1];
    const float* wf    = (const float*)d_in[2];
    const float* Wih0  = (const float*)d_in[3];
    const float* Whh0  = (const float*)d_in[4];
    const float* b0    = (const float*)d_in[5];
    const float* Wih1  = (const float*)d_in[6];
    const float* Whh1  = (const float*)d_in[7];
    const float* b1    = (const float*)d_in[8];
    const float* headW = (const float*)d_in[9];
    const float* headb = (const float*)d_in[10];
    float* out = (float*)d_out;

    __nv_bfloat16 *xph, *xpl, *xdh, *xdl, *y0h, *y0l, *zb;
    __nv_bfloat16 *h1h, *h1l, *h0h, *h0l;
    __nv_bfloat16 *w0h, *w0l, *w1hhh, *w1hhl, *w1ihh, *w1ihl, *wx0h, *wx0l;
    float *pred, *c0, *c1, *h1f, *h0f, *br0, *br1;
    cudaGetSymbolAddress((void**)&xph,   g_xph);
    cudaGetSymbolAddress((void**)&xpl,   g_xpl);
    cudaGetSymbolAddress((void**)&xdh,   g_xdh);
    cudaGetSymbolAddress((void**)&xdl,   g_xdl);
    cudaGetSymbolAddress((void**)&pred,  g_pred);
    cudaGetSymbolAddress((void**)&y0h,   g_y0h);
    cudaGetSymbolAddress((void**)&y0l,   g_y0l);
    cudaGetSymbolAddress((void**)&zb,    g_zb);
    cudaGetSymbolAddress((void**)&c0,    g_c0);
    cudaGetSymbolAddress((void**)&c1,    g_c1);
    cudaGetSymbolAddress((void**)&h1h,   g_h1h);
    cudaGetSymbolAddress((void**)&h1l,   g_h1l);
    cudaGetSymbolAddress((void**)&h0h,   g_h0h);
    cudaGetSymbolAddress((void**)&h0l,   g_h0l);
    cudaGetSymbolAddress((void**)&h1f,   g_h1f);
    cudaGetSymbolAddress((void**)&h0f,   g_h0f);
    cudaGetSymbolAddress((void**)&w0h,   g_w0h);
    cudaGetSymbolAddress((void**)&w0l,   g_w0l);
    cudaGetSymbolAddress((void**)&w1hhh, g_w1hh_h);
    cudaGetSymbolAddress((void**)&w1hhl, g_w1hh_l);
    cudaGetSymbolAddress((void**)&w1ihh, g_w1ih_h);
    cudaGetSymbolAddress((void**)&w1ihl, g_w1ih_l);
    cudaGetSymbolAddress((void**)&wx0h,  g_wx0h);
    cudaGetSymbolAddress((void**)&wx0l,  g_wx0l);
    cudaGetSymbolAddress((void**)&br0,   g_br0);
    cudaGetSymbolAddress((void**)&br1,   g_br1);

    cudaFuncSetAttribute(cell_mma, cudaFuncAttributeMaxDynamicSharedMemorySize,
                         SMEM_TOTAL);
    cudaFuncSetAttribute(enc_step, cudaFuncAttributeMaxDynamicSharedMemorySize,
                         SMEM_TOTAL);

    dim3 grid1(4, 32), grid2(4, 64), blk(256);

    prep_kernel<<<T_HIST, NB>>>(veg, wh, wf, xph, xpl, xdh, xdl, pred);
    wprep_kernel<<<GROW, 128>>>(Wih0, Whh0, b0, Wih1, Whh1, b1,
                                w0h, w0l, w1hhh, w1hhl, w1ihh, w1ihl,
                                wx0h, wx0l, br0, br1);
    zero_kernel<<<(HB + 255) / 256, 256>>>(c0, c1, zb);

    // L0(0) alone
    cell_mma<<<grid1, blk, SMEM_TOTAL>>>(
        zb, zb, w0h, w0l, xph, xpl, wx0h, wx0l,
        1, XPW, br0, c0, h0f, y0h, y0l);

    // merged wavefront: t = 0..148 computes L1(t) and L0(t+1) concurrently
    for (int t = 0; t < T_HIST - 1; t++) {
        const __nv_bfloat16* h1pH = (t == 0) ? zb : (h1h + ((t + 1) & 1) * HB);
        const __nv_bfloat16* h1pL = (t == 0) ? zb : (h1l + ((t + 1) & 1) * HB);
        enc_step<<<grid2, blk, SMEM_TOTAL>>>(
            h1pH, h1pL, w1hhh, w1hhl,
            y0h + (size_t)t * HB, y0l + (size_t)t * HB, w1ihh, w1ihl,
            br1, c1, h1f, h1h + (t & 1) * HB, h1l + (t & 1) * HB,
            xph + (size_t)(t + 1) * NB * XPW, xpl + (size_t)(t + 1) * NB * XPW,
            w0h, w0l, wx0h, wx0l,
            br0, c0, h0f,
            y0h + (size_t)(t + 1) * HB, y0l + (size_t)(t + 1) * HB);
    }
    // final L1(149): reads h1[148&1=0], writes h1[149&1=1]
    {
        int t = T_HIST - 1;
        cell_mma<<<grid1, blk, SMEM_TOTAL>>>(
            h1h + ((t + 1) & 1) * HB, h1l + ((t + 1) & 1) * HB, w1hhh, w1hhl,
            y0h + (size_t)t * HB, y0l + (size_t)t * HB, w1ihh, w1ihl,
            8, HID, br1, c1, h1f, h1h + (t & 1) * HB, h1l + (t & 1) * HB);
    }

    // decoder (serial dependence)
    // h1 ping-pong: encoder ended writing index 1 (t=149). Decoder step t
    // reads index (t+1)&1 and writes index t&1  (t=0: read 1, write 0). Same
    // phase convention as round 3 (verified correct).
    for (int t = 0; t < T_FUT; t++) {
        const __nv_bfloat16* hpH = (t == 0) ? (y0h + (size_t)(T_HIST - 1) * HB)
                                            : (h0h + ((t + 1) & 1) * HB);
        const __nv_bfloat16* hpL = (t == 0) ? (y0l + (size_t)(T_HIST - 1) * HB)
                                            : (h0l + ((t + 1) & 1) * HB);
        cell_mma<<<grid1, blk, SMEM_TOTAL>>>(
            hpH, hpL, w0h, w0l, xdh, xdl, wx0h, wx0l,
            1, XPW, br0, c0, h0f, h0h + (t & 1) * HB, h0l + (t & 1) * HB);
        cell_mma<<<grid1, blk, SMEM_TOTAL>>>(
            h1h + ((t + 1) & 1) * HB, h1l + ((t + 1) & 1) * HB, w1hhh, w1hhl,
            h0h + (t & 1) * HB, h0l + (t & 1) * HB, w1ihh, w1ihl,
            8, HID, br1, c1, h1f, h1h + (t & 1) * HB, h1l + (t & 1) * HB);
        const float* wfn = (t < T_FUT - 1) ? (wf + (t + 1) * WEA) : nullptr;
        head_kernel<<<NB, 128>>>(h1f, headW, headb, pred,
                                 out + t * VEG, wfn, xdh, xdl);
    }
}